// round 1
// baseline (speedup 1.0000x reference)
#include <cuda_runtime.h>
#include <cuda_bf16.h>
#include <cstdint>

// Problem constants
#define NNODES   50000
#define NEDGES   800000
#define FEATDIM  64
#define NRELS    200
#define SCHUNKS  8      // chunks per relation in edge GEMM grid

// -------- scratch (device globals; no allocation allowed) --------
__device__ int   g_hist[NRELS];
__device__ int   g_off[NRELS + 1];
__device__ int   g_cur[NRELS];
__device__ int   g_cnt[NNODES];
__device__ int   g_src_s[NEDGES];
__device__ int   g_dst_s[NEDGES];
__device__ float g_relB[NRELS * FEATDIM];

// -------- f32x2 helpers --------
#define FMA2(acc, a, b) \
    asm("fma.rn.f32x2 %0, %1, %2, %0;" : "+l"(acc) : "l"(a), "l"(b))
#define PACK_DUP(h2, h) \
    asm("mov.b64 %0, {%1, %1};" : "=l"(h2) : "f"(h))
#define UNPACK2(lo, hi, v) \
    asm("mov.b64 {%0, %1}, %2;" : "=f"(lo), "=f"(hi) : "l"(v))

__device__ __forceinline__ void red_add_v4(float* p, float a, float b, float c, float d) {
    asm volatile("red.global.add.v4.f32 [%0], {%1,%2,%3,%4};"
                 :: "l"(p), "f"(a), "f"(b), "f"(c), "f"(d) : "memory");
}

// -------- K0: zero init --------
__global__ void k_init(float* out, int total) {
    int i = blockIdx.x * blockDim.x + threadIdx.x;
    int stride = gridDim.x * blockDim.x;
    for (int j = i; j < total; j += stride) out[j] = 0.0f;
    for (int j = i; j < NNODES; j += stride) g_cnt[j] = 0;
    for (int j = i; j < NRELS; j += stride) g_hist[j] = 0;
}

// -------- K1: relB[t][j] = sum_k rel[t][k] * (W1[k][j] + W4[k][j]) --------
__global__ void k_relB(const float* __restrict__ rel, const float* __restrict__ Wn) {
    int t = blockIdx.x;
    int j = threadIdx.x;
    float s = 0.0f;
    #pragma unroll 8
    for (int k = 0; k < 64; k++) {
        s += rel[t * 64 + k] * (Wn[k * 64 + j] + Wn[(192 + k) * 64 + j]);
    }
    g_relB[t * 64 + j] = s;
}

// -------- K2: etype histogram (smem-aggregated) + dst degree --------
__global__ void k_hist(const int* __restrict__ etype, const int* __restrict__ dst, int E) {
    __shared__ int sh[NRELS];
    for (int i = threadIdx.x; i < NRELS; i += blockDim.x) sh[i] = 0;
    __syncthreads();
    int i0 = blockIdx.x * blockDim.x + threadIdx.x;
    int stride = gridDim.x * blockDim.x;
    for (int e = i0; e < E; e += stride) {
        atomicAdd(&sh[etype[e]], 1);
        atomicAdd(&g_cnt[dst[e]], 1);
    }
    __syncthreads();
    for (int i = threadIdx.x; i < NRELS; i += blockDim.x)
        if (sh[i]) atomicAdd(&g_hist[i], sh[i]);
}

// -------- K3: exclusive scan of histogram (single block) --------
__global__ void k_scan() {
    __shared__ int tmp[256];
    int tid = threadIdx.x;
    int v = (tid < NRELS) ? g_hist[tid] : 0;
    tmp[tid] = v;
    __syncthreads();
    #pragma unroll
    for (int d = 1; d < 256; d <<= 1) {
        int t = (tid >= d) ? tmp[tid - d] : 0;
        __syncthreads();
        tmp[tid] += t;
        __syncthreads();
    }
    if (tid < NRELS) {
        int off = tmp[tid] - v;  // exclusive
        g_off[tid] = off;
        g_cur[tid] = off;
    }
    if (tid == 255) g_off[NRELS] = tmp[255];
}

// -------- K4: counting-sort scatter (block-aggregated cursors) --------
#define KPT 8
__global__ void k_sort(const int* __restrict__ src, const int* __restrict__ dst,
                       const int* __restrict__ etype, int E) {
    __shared__ int lh[NRELS];
    __shared__ int lbase[NRELS];
    int tid = threadIdx.x;
    for (int i = tid; i < NRELS; i += blockDim.x) lh[i] = 0;
    __syncthreads();
    int base = blockIdx.x * blockDim.x * KPT;
    int et[KPT], rk[KPT];
    #pragma unroll
    for (int q = 0; q < KPT; q++) {
        int e = base + q * blockDim.x + tid;
        if (e < E) {
            et[q] = etype[e];
            rk[q] = atomicAdd(&lh[et[q]], 1);
        } else {
            et[q] = -1;
        }
    }
    __syncthreads();
    for (int i = tid; i < NRELS; i += blockDim.x) {
        int c = lh[i];
        lbase[i] = c ? atomicAdd(&g_cur[i], c) : 0;
    }
    __syncthreads();
    #pragma unroll
    for (int q = 0; q < KPT; q++) {
        if (et[q] >= 0) {
            int e = base + q * blockDim.x + tid;
            int pos = lbase[et[q]] + rk[q];
            g_src_s[pos] = src[e];
            g_dst_s[pos] = dst[e];
        }
    }
}

// -------- K5: edge GEMM (per-relation C_t in SMEM, 128-edge tiles) --------
// smem layout: Cs[4096] | Hs[128*65] | rB[64] | Ds[128]
#define HS_STRIDE 65
#define EDGE_SMEM ((4096 + 128 * HS_STRIDE + 64) * 4 + 128 * 4)

__global__ __launch_bounds__(256) void k_edge(const float* __restrict__ feat,
                                              const float* __restrict__ rel,
                                              const float* __restrict__ Wn,
                                              float* __restrict__ out) {
    extern __shared__ float smem[];
    float* Cs = smem;                         // 64x64
    float* Hs = smem + 4096;                  // 128 x 65
    float* rB = Hs + 128 * HS_STRIDE;         // 64
    int*   Ds = (int*)(rB + 64);              // 128

    int t = blockIdx.x >> 3;       // SCHUNKS = 8
    int c = blockIdx.x & 7;
    int tid = threadIdx.x;

    int beg = g_off[t], end = g_off[t + 1];
    int n = end - beg;
    int s0 = beg + (n * c) / SCHUNKS;
    int s1 = beg + (n * (c + 1)) / SCHUNKS;

    // C_t[k][j] = W1[k][j] + W3[k][j] + rel[t][k] * W2[k][j]
    for (int idx = tid; idx < 4096; idx += 256) {
        int k = idx >> 6;
        Cs[idx] = Wn[idx] + Wn[8192 + idx] + rel[t * 64 + k] * Wn[4096 + idx];
    }
    if (tid < 64) rB[tid] = g_relB[t * 64 + tid];
    __syncthreads();

    int ty = tid >> 3;      // 0..31 : edge group (4 edges each)
    int tx = tid & 7;       // 0..7  : output group (8 cols)
    int jj = tx * 8;

    float rb[8];
    #pragma unroll
    for (int q = 0; q < 8; q++) rb[q] = rB[jj + q];

    int hbase = ty * 4 * HS_STRIDE;

    for (int base = s0; base < s1; base += 128) {
        int m = min(128, s1 - base);
        __syncthreads();   // previous tile fully consumed

        if (tid < 128) Ds[tid] = (tid < m) ? g_dst_s[base + tid] : -1;

        // gather feat rows -> Hs (scalar store, stride 65 kills LDS conflicts)
        #pragma unroll
        for (int p = 0; p < 8; p++) {
            int idx = p * 256 + tid;         // float4 slot 0..2047
            int e = idx >> 4, c4 = idx & 15;
            float4 v = make_float4(0.f, 0.f, 0.f, 0.f);
            if (e < m) {
                int s = g_src_s[base + e];
                v = *(const float4*)&feat[(size_t)s * 64 + c4 * 4];
            }
            float* hp = &Hs[e * HS_STRIDE + c4 * 4];
            hp[0] = v.x; hp[1] = v.y; hp[2] = v.z; hp[3] = v.w;
        }
        __syncthreads();

        unsigned long long a0[4], a1[4], a2[4], a3[4];
        #pragma unroll
        for (int i = 0; i < 4; i++) { a0[i] = 0ull; a1[i] = 0ull; a2[i] = 0ull; a3[i] = 0ull; }

        #pragma unroll 4
        for (int k = 0; k < 64; k++) {
            const float* crow = &Cs[(k << 6) + jj];
            ulonglong2 cA = *reinterpret_cast<const ulonglong2*>(crow);
            ulonglong2 cB = *reinterpret_cast<const ulonglong2*>(crow + 4);
            #pragma unroll
            for (int i = 0; i < 4; i++) {
                float h = Hs[hbase + i * HS_STRIDE + k];
                unsigned long long h2;
                PACK_DUP(h2, h);
                FMA2(a0[i], h2, cA.x);
                FMA2(a1[i], h2, cA.y);
                FMA2(a2[i], h2, cB.x);
                FMA2(a3[i], h2, cB.y);
            }
        }

        // epilogue: add bias, scatter-reduce
        #pragma unroll
        for (int i = 0; i < 4; i++) {
            int e = ty * 4 + i;
            if (e < m) {
                int d = Ds[e];
                float v0, v1, v2, v3, v4, v5, v6, v7;
                UNPACK2(v0, v1, a0[i]);
                UNPACK2(v2, v3, a1[i]);
                UNPACK2(v4, v5, a2[i]);
                UNPACK2(v6, v7, a3[i]);
                v0 += rb[0]; v1 += rb[1]; v2 += rb[2]; v3 += rb[3];
                v4 += rb[4]; v5 += rb[5]; v6 += rb[6]; v7 += rb[7];
                float* p = out + (size_t)d * 64 + jj;
                red_add_v4(p,     v0, v1, v2, v3);
                red_add_v4(p + 4, v4, v5, v6, v7);
            }
        }
    }
}

// -------- K6: finalize out = out / max(cnt,1) + feat @ loop_weight --------
__global__ __launch_bounds__(256) void k_final(const float* __restrict__ feat,
                                               const float* __restrict__ LW,
                                               float* __restrict__ out, int N) {
    __shared__ float Ls[4096];
    __shared__ float Fs[32 * HS_STRIDE];
    int tid = threadIdx.x;
    for (int idx = tid; idx < 4096; idx += 256) Ls[idx] = LW[idx];

    int n0 = blockIdx.x * 32;
    #pragma unroll
    for (int p = 0; p < 2; p++) {
        int idx = p * 256 + tid;
        int e = idx >> 4, c4 = idx & 15;
        int node = n0 + e;
        float4 v = make_float4(0.f, 0.f, 0.f, 0.f);
        if (node < N) v = *(const float4*)&feat[(size_t)node * 64 + c4 * 4];
        float* hp = &Fs[e * HS_STRIDE + c4 * 4];
        hp[0] = v.x; hp[1] = v.y; hp[2] = v.z; hp[3] = v.w;
    }
    __syncthreads();

    int ty = tid >> 3, tx = tid & 7, jj = tx * 8;
    int node = n0 + ty;

    unsigned long long a0 = 0, a1 = 0, a2 = 0, a3 = 0;
    #pragma unroll 4
    for (int k = 0; k < 64; k++) {
        const float* crow = &Ls[(k << 6) + jj];
        ulonglong2 cA = *reinterpret_cast<const ulonglong2*>(crow);
        ulonglong2 cB = *reinterpret_cast<const ulonglong2*>(crow + 4);
        float h = Fs[ty * HS_STRIDE + k];
        unsigned long long h2;
        PACK_DUP(h2, h);
        FMA2(a0, h2, cA.x);
        FMA2(a1, h2, cA.y);
        FMA2(a2, h2, cB.x);
        FMA2(a3, h2, cB.y);
    }

    if (node < N) {
        int cnt = g_cnt[node];
        float inv = 1.0f / (float)(cnt > 0 ? cnt : 1);
        float* p = out + (size_t)node * 64 + jj;
        float4 s0 = *(float4*)p;
        float4 s1 = *(float4*)(p + 4);
        float v0, v1, v2, v3, v4, v5, v6, v7;
        UNPACK2(v0, v1, a0);
        UNPACK2(v2, v3, a1);
        UNPACK2(v4, v5, a2);
        UNPACK2(v6, v7, a3);
        float4 o0 = make_float4(s0.x * inv + v0, s0.y * inv + v1, s0.z * inv + v2, s0.w * inv + v3);
        float4 o1 = make_float4(s1.x * inv + v4, s1.y * inv + v5, s1.z * inv + v6, s1.w * inv + v7);
        *(float4*)p = o0;
        *(float4*)(p + 4) = o1;
    }
}

// -------- launch --------
extern "C" void kernel_launch(void* const* d_in, const int* in_sizes, int n_in,
                              void* d_out, int out_size) {
    const float* feat = (const float*)d_in[0];
    const float* rel  = (const float*)d_in[1];
    const float* Wn   = (const float*)d_in[2];
    const float* LW   = (const float*)d_in[3];
    const int*   src  = (const int*)d_in[4];
    const int*   dst  = (const int*)d_in[5];
    const int*   et   = (const int*)d_in[6];
    float* out = (float*)d_out;

    int E = in_sizes[4];
    int N = in_sizes[0] / FEATDIM;

    cudaFuncSetAttribute(k_edge, cudaFuncAttributeMaxDynamicSharedMemorySize, EDGE_SMEM);

    k_init<<<1024, 256>>>(out, N * FEATDIM);
    k_relB<<<NRELS, 64>>>(rel, Wn);
    k_hist<<<512, 256>>>(et, dst, E);
    k_scan<<<1, 256>>>();
    k_sort<<<(E + 256 * KPT - 1) / (256 * KPT), 256>>>(src, dst, et, E);
    k_edge<<<NRELS * SCHUNKS, 256, EDGE_SMEM>>>(feat, rel, Wn, out);
    k_final<<<(N + 31) / 32, 256>>>(feat, LW, out, N);
}

// round 3
// speedup vs baseline: 1.5931x; 1.5931x over previous
#include <cuda_runtime.h>
#include <cuda_bf16.h>
#include <cstdint>

#define NN      50000
#define NE      800000
#define NRELS   200
#define NB_SCAN 98          // ceil(NN / 512)

// -------- scratch (device globals; allocation is forbidden) --------
__device__ int   g_cnt[NN];           // dst degree
__device__ int   g_bsum[NB_SCAN];
__device__ int   g_boff[NB_SCAN];
__device__ int   g_off[NN + 1];
__device__ int   g_cur[NN];
__device__ int2  g_es[NE];            // (src, etype) sorted by dst
__device__ float g_relB[NRELS * 64];  // rel @ (W1+W4)
__device__ float g_A[NN * 64];        // (Σ h)/cnt
__device__ float g_B[NN * 64];        // (Σ h⊙r)/cnt
__device__ float g_C[NN * 64];        // (Σ relB)/cnt

// -------- f32x2 helpers --------
#define FMA2(acc, a, b) \
    asm("fma.rn.f32x2 %0, %1, %2, %0;" : "+l"(acc) : "l"(a), "l"(b))
#define PACK_DUP(h2, h) \
    asm("mov.b64 %0, {%1, %1};" : "=l"(h2) : "f"(h))
#define UNPACK2(lo, hi, v) \
    asm("mov.b64 {%0, %1}, %2;" : "=f"(lo), "=f"(hi) : "l"(v))

// -------- K1: relB[t][j] = sum_k rel[t][k] * (W1[k][j] + W4[k][j]) --------
__global__ void k_relB(const float* __restrict__ rel, const float* __restrict__ Wn) {
    int t = blockIdx.x;
    int j = threadIdx.x;
    float s = 0.0f;
    #pragma unroll 8
    for (int k = 0; k < 64; k++)
        s += rel[t * 64 + k] * (Wn[k * 64 + j] + Wn[(192 + k) * 64 + j]);
    g_relB[t * 64 + j] = s;
}

// -------- K2: zero degree counters --------
__global__ void k_zero() {
    int i = blockIdx.x * blockDim.x + threadIdx.x;
    int stride = gridDim.x * blockDim.x;
    for (int j = i; j < NN; j += stride) g_cnt[j] = 0;
}

// -------- K3: dst degree histogram --------
__global__ void k_deg(const int* __restrict__ dst, int E) {
    int i = blockIdx.x * blockDim.x + threadIdx.x;
    int stride = gridDim.x * blockDim.x;
    for (int e = i; e < E; e += stride) atomicAdd(&g_cnt[dst[e]], 1);
}

// -------- K4a: per-block exclusive scan (512 elems / block) --------
__global__ void kscanA() {
    __shared__ int tmp[512];
    int b = blockIdx.x, tid = threadIdx.x;
    int i = b * 512 + tid;
    int v = (i < NN) ? g_cnt[i] : 0;
    tmp[tid] = v;
    __syncthreads();
    #pragma unroll
    for (int d = 1; d < 512; d <<= 1) {
        int t = (tid >= d) ? tmp[tid - d] : 0;
        __syncthreads();
        tmp[tid] += t;
        __syncthreads();
    }
    if (i < NN) g_off[i] = tmp[tid] - v;       // exclusive within block
    if (tid == 511) g_bsum[b] = tmp[511];
}

// -------- K4b: scan the block sums --------
__global__ void kscanB() {
    __shared__ int tmp[128];
    int tid = threadIdx.x;
    int v = (tid < NB_SCAN) ? g_bsum[tid] : 0;
    tmp[tid] = v;
    __syncthreads();
    #pragma unroll
    for (int d = 1; d < 128; d <<= 1) {
        int t = (tid >= d) ? tmp[tid - d] : 0;
        __syncthreads();
        tmp[tid] += t;
        __syncthreads();
    }
    if (tid < NB_SCAN) g_boff[tid] = tmp[tid] - v;
}

// -------- K4c: add block offsets; init cursors --------
__global__ void kscanC(int E) {
    int i = blockIdx.x * blockDim.x + threadIdx.x;
    int stride = gridDim.x * blockDim.x;
    for (int j = i; j < NN; j += stride) {
        int off = g_off[j] + g_boff[j >> 9];
        g_off[j] = off;
        g_cur[j] = off;
    }
    if (i == 0) g_off[NN] = E;
}

// -------- K5: counting-sort scatter by dst --------
__global__ void k_scatter(const int* __restrict__ src, const int* __restrict__ dst,
                          const int* __restrict__ etype, int E) {
    int i = blockIdx.x * blockDim.x + threadIdx.x;
    int stride = gridDim.x * blockDim.x;
    for (int e = i; e < E; e += stride) {
        int d = dst[e];
        int pos = atomicAdd(&g_cur[d], 1);
        g_es[pos] = make_int2(src[e], etype[e]);
    }
}

// -------- K6: per-dst aggregation (one warp per node, no float atomics) --------
__global__ __launch_bounds__(256) void k_agg(const float* __restrict__ feat,
                                             const float* __restrict__ rel) {
    int wid = (blockIdx.x * 256 + threadIdx.x) >> 5;
    int lane = threadIdx.x & 31;
    if (wid >= NN) return;
    int beg = g_off[wid], end = g_off[wid + 1];

    const float2* f2  = (const float2*)feat;
    const float2* r2  = (const float2*)rel;
    const float2* rb2 = (const float2*)g_relB;

    float ax = 0.f, ay = 0.f, bx = 0.f, by = 0.f, cx = 0.f, cy = 0.f;

    if (beg < end) {
        int2 e = g_es[beg];
        for (int i = beg; i < end; i++) {
            int2 en = (i + 1 < end) ? g_es[i + 1] : e;   // prefetch next edge key
            float2 h  = f2[e.x * 32 + lane];
            float2 r  = r2[e.y * 32 + lane];
            float2 rb = rb2[e.y * 32 + lane];
            ax += h.x;  ay += h.y;
            bx = fmaf(h.x, r.x, bx);
            by = fmaf(h.y, r.y, by);
            cx += rb.x; cy += rb.y;
            e = en;
        }
    }
    float inv = 1.0f / (float)((end - beg) > 0 ? (end - beg) : 1);
    int o = wid * 32 + lane;
    ((float2*)g_A)[o] = make_float2(ax * inv, ay * inv);
    ((float2*)g_B)[o] = make_float2(bx * inv, by * inv);
    ((float2*)g_C)[o] = make_float2(cx * inv, cy * inv);
}

// -------- K7: out = A@W13 + B@W2 + C + feat@LW  (32 nodes / block) --------
#define TS 65
#define FSMEM ((3 * 4096 + 3 * 32 * TS) * 4)

__global__ __launch_bounds__(256) void k_final(const float* __restrict__ feat,
                                               const float* __restrict__ Wn,
                                               const float* __restrict__ LW,
                                               float* __restrict__ out, int N) {
    extern __shared__ float smem[];
    float* W13s = smem;                 // 4096
    float* W2s  = smem + 4096;          // 4096
    float* LWs  = smem + 8192;          // 4096
    float* As   = smem + 12288;         // 32*65
    float* Bs   = As + 32 * TS;
    float* Fs   = Bs + 32 * TS;

    int tid = threadIdx.x;
    for (int idx = tid; idx < 4096; idx += 256) {
        W13s[idx] = Wn[idx] + Wn[8192 + idx];
        W2s[idx]  = Wn[4096 + idx];
        LWs[idx]  = LW[idx];
    }

    int n0 = blockIdx.x * 32;
    // load A, B, feat tiles (32 nodes x 64 floats each) as float4
    #pragma unroll
    for (int p = 0; p < 6; p++) {
        int idx = p * 256 + tid;        // 0..1535 : matrix = idx/512, slot = idx%512
        int mat = idx >> 9;
        int slot = idx & 511;
        int e = slot >> 4, c4 = slot & 15;
        int node = n0 + e;
        const float* srcp = (mat == 0) ? g_A : (mat == 1) ? g_B : feat;
        float* dstp = (mat == 0) ? As : (mat == 1) ? Bs : Fs;
        float4 v = make_float4(0.f, 0.f, 0.f, 0.f);
        if (node < N) v = *(const float4*)&srcp[(size_t)node * 64 + c4 * 4];
        float* hp = &dstp[e * TS + c4 * 4];
        hp[0] = v.x; hp[1] = v.y; hp[2] = v.z; hp[3] = v.w;
    }
    __syncthreads();

    int ty = tid >> 3, tx = tid & 7, jj = tx * 8;
    int node = n0 + ty;

    unsigned long long a0 = 0, a1 = 0, a2 = 0, a3 = 0;
    #pragma unroll 4
    for (int k = 0; k < 64; k++) {
        float la = As[ty * TS + k];
        float lb = Bs[ty * TS + k];
        float lf = Fs[ty * TS + k];
        unsigned long long la2, lb2, lf2;
        PACK_DUP(la2, la); PACK_DUP(lb2, lb); PACK_DUP(lf2, lf);

        const float* w13 = &W13s[(k << 6) + jj];
        const float* w2  = &W2s[(k << 6) + jj];
        const float* lw  = &LWs[(k << 6) + jj];
        ulonglong2 wA = *reinterpret_cast<const ulonglong2*>(w13);
        ulonglong2 wB = *reinterpret_cast<const ulonglong2*>(w13 + 4);
        ulonglong2 vA = *reinterpret_cast<const ulonglong2*>(w2);
        ulonglong2 vB = *reinterpret_cast<const ulonglong2*>(w2 + 4);
        ulonglong2 uA = *reinterpret_cast<const ulonglong2*>(lw);
        ulonglong2 uB = *reinterpret_cast<const ulonglong2*>(lw + 4);

        FMA2(a0, la2, wA.x); FMA2(a1, la2, wA.y); FMA2(a2, la2, wB.x); FMA2(a3, la2, wB.y);
        FMA2(a0, lb2, vA.x); FMA2(a1, lb2, vA.y); FMA2(a2, lb2, vB.x); FMA2(a3, lb2, vB.y);
        FMA2(a0, lf2, uA.x); FMA2(a1, lf2, uA.y); FMA2(a2, lf2, uB.x); FMA2(a3, lf2, uB.y);
    }

    if (node < N) {
        float4 c0 = *(const float4*)&g_C[(size_t)node * 64 + jj];
        float4 c1 = *(const float4*)&g_C[(size_t)node * 64 + jj + 4];
        float v0, v1, v2, v3, v4, v5, v6, v7;
        UNPACK2(v0, v1, a0); UNPACK2(v2, v3, a1);
        UNPACK2(v4, v5, a2); UNPACK2(v6, v7, a3);
        float* p = out + (size_t)node * 64 + jj;
        *(float4*)p       = make_float4(v0 + c0.x, v1 + c0.y, v2 + c0.z, v3 + c0.w);
        *(float4*)(p + 4) = make_float4(v4 + c1.x, v5 + c1.y, v6 + c1.z, v7 + c1.w);
    }
}

// -------- launch --------
extern "C" void kernel_launch(void* const* d_in, const int* in_sizes, int n_in,
                              void* d_out, int out_size) {
    const float* feat = (const float*)d_in[0];
    const float* rel  = (const float*)d_in[1];
    const float* Wn   = (const float*)d_in[2];
    const float* LW   = (const float*)d_in[3];
    const int*   src  = (const int*)d_in[4];
    const int*   dst  = (const int*)d_in[5];
    const int*   et   = (const int*)d_in[6];
    float* out = (float*)d_out;

    int E = in_sizes[4];
    int N = in_sizes[0] / 64;

    cudaFuncSetAttribute(k_final, cudaFuncAttributeMaxDynamicSharedMemorySize, FSMEM);

    k_relB<<<NRELS, 64>>>(rel, Wn);
    k_zero<<<64, 256>>>();
    k_deg<<<512, 256>>>(dst, E);
    kscanA<<<NB_SCAN, 512>>>();
    kscanB<<<1, 128>>>();
    kscanC<<<64, 256>>>(E);
    k_scatter<<<1024, 256>>>(src, dst, et, E);
    k_agg<<<(NN * 32 + 255) / 256, 256>>>(feat, rel);
    k_final<<<(N + 31) / 32, 256, FSMEM>>>(feat, Wn, LW, out, N);
}